// round 4
// baseline (speedup 1.0000x reference)
#include <cuda_runtime.h>
#include <cuda_bf16.h>
#include <math.h>
#include <stdint.h>

#define B_  16
#define L_  1024
#define C_  128
#define H_  512
#define LC_ (L_*C_)      // 131072
#define M_  (B_*L_)      // 16384

// ---------------- device scratch ----------------
__device__ float g_eps[M_*C_];
__device__ float g_za [M_*C_];
__device__ float g_zb [M_*C_];
__device__ float g_ent[LC_];
__device__ float g_p1[(L_/2)*(C_/2)];
__device__ float g_p2[(L_/4)*(C_/4)];
__device__ float g_p3[(L_/8)*(C_/8)];
__device__ float g_part[1024];
__device__ float g_T[4];
__device__ float g_stats[2];
// z splits [M,128] bf16
__device__ __nv_bfloat16 g_za0[M_*C_], g_za1[M_*C_], g_za2[M_*C_];
// h splits [M,512] bf16 (written by GEMM1 epilogue)
__device__ __nv_bfloat16 g_h0[M_*H_], g_h1[M_*H_], g_h2[M_*H_];
// weight splits, transposed [N,K] row-major (K contiguous)
__device__ __nv_bfloat16 g_b1t0[H_*C_], g_b1t1[H_*C_], g_b1t2[H_*C_]; // [512,128]
__device__ __nv_bfloat16 g_b2t0[C_*H_], g_b2t1[C_*H_], g_b2t2[C_*H_]; // [128,512]

// ---------------- helpers ----------------
__device__ __forceinline__ uint32_t smem_u32(const void* p) {
    uint32_t a;
    asm("{ .reg .u64 t; cvta.to.shared.u64 t, %1; cvt.u32.u64 %0, t; }" : "=r"(a) : "l"(p));
    return a;
}
__device__ __forceinline__ void cp_async16(uint32_t s, const void* g) {
    asm volatile("cp.async.cg.shared.global [%0], [%1], 16;" :: "r"(s), "l"(g) : "memory");
}
__device__ __forceinline__ void ldsm_x4(uint32_t* r, uint32_t addr) {
    asm volatile("ldmatrix.sync.aligned.m8n8.x4.shared.b16 {%0,%1,%2,%3}, [%4];"
                 : "=r"(r[0]), "=r"(r[1]), "=r"(r[2]), "=r"(r[3]) : "r"(addr));
}
__device__ __forceinline__ void mma16816(float* d, const uint32_t* a, const uint32_t* b) {
    asm volatile(
        "mma.sync.aligned.m16n8k16.row.col.f32.bf16.bf16.f32 "
        "{%0,%1,%2,%3}, {%4,%5,%6,%7}, {%8,%9}, {%0,%1,%2,%3};"
        : "+f"(d[0]), "+f"(d[1]), "+f"(d[2]), "+f"(d[3])
        : "r"(a[0]), "r"(a[1]), "r"(a[2]), "r"(a[3]), "r"(b[0]), "r"(b[1]));
}
__device__ __forceinline__ float gelu_f(float x) {
    float x3 = x * x * x;
    float u  = 0.7978845608028654f * (x + 0.044715f * x3);
    return 0.5f * x * (1.0f + tanhf(u));
}
__device__ __forceinline__ void split3(float x, unsigned short& h0, unsigned short& h1, unsigned short& h2) {
    __nv_bfloat16 b0 = __float2bfloat16_rn(x);
    float r1 = x - __bfloat162float(b0);
    __nv_bfloat16 b1 = __float2bfloat16_rn(r1);
    float r2 = r1 - __bfloat162float(b1);
    __nv_bfloat16 b2 = __float2bfloat16_rn(r2);
    h0 = __bfloat16_as_ushort(b0);
    h1 = __bfloat16_as_ushort(b1);
    h2 = __bfloat16_as_ushort(b2);
}

// ---------------- weight prep: transpose + 3-way split (run once) -------
__global__ __launch_bounds__(256) void prep_k(const float* __restrict__ W1, const float* __restrict__ W2)
{
    int t = blockIdx.x * 256 + threadIdx.x;   // 131072 total
    float x; int idx;
    __nv_bfloat16 *d0, *d1, *d2;
    if (t < H_ * C_) {                        // B1t [512,128] from W1[128,512]
        idx = t; int n = idx >> 7, k = idx & 127;
        x = W1[k * H_ + n];
        d0 = g_b1t0; d1 = g_b1t1; d2 = g_b1t2;
    } else {                                  // B2t [128,512] from W2[512,128]
        idx = t - H_ * C_; int n = idx >> 9, k = idx & 511;
        x = W2[k * C_ + n];
        d0 = g_b2t0; d1 = g_b2t1; d2 = g_b2t2;
    }
    unsigned short h0, h1, h2;
    split3(x, h0, h1, h2);
    d0[idx] = __ushort_as_bfloat16(h0);
    d1[idx] = __ushort_as_bfloat16(h1);
    d2[idx] = __ushort_as_bfloat16(h2);
}

// ---------------- z split: fp32 [M,128] -> 3x bf16 ----------------------
__global__ __launch_bounds__(256) void splitz_k(const float* __restrict__ z)
{
    int i = blockIdx.x * 256 + threadIdx.x;   // i < M_*C_/4
    float4 v = *(const float4*)(z + (size_t)i * 4);
    float x[4] = { v.x, v.y, v.z, v.w };
    unsigned short s0[4], s1[4], s2[4];
#pragma unroll
    for (int j = 0; j < 4; j++) split3(x[j], s0[j], s1[j], s2[j]);
    uint2 p0 = make_uint2((uint32_t)s0[0] | ((uint32_t)s0[1] << 16), (uint32_t)s0[2] | ((uint32_t)s0[3] << 16));
    uint2 p1 = make_uint2((uint32_t)s1[0] | ((uint32_t)s1[1] << 16), (uint32_t)s1[2] | ((uint32_t)s1[3] << 16));
    uint2 p2 = make_uint2((uint32_t)s2[0] | ((uint32_t)s2[1] << 16), (uint32_t)s2[2] | ((uint32_t)s2[3] << 16));
    ((uint2*)g_za0)[i] = p0;
    ((uint2*)g_za1)[i] = p1;
    ((uint2*)g_za2)[i] = p2;
}

// ---------------- split-fp32 GEMM via bf16 mma.sync ---------------------
// C[M,Ntot] = A[M,KTOT] @ B[Ntot,KTOT]^T, A/B given as 3-term bf16 splits.
// CTA tile 128x128, BK=32, 8 warps (64x32 warp tile), double-buffered cp.async.
static constexpr int TERMB = 10240;   // bytes per 128x32 bf16 tile (row stride 80B)
static constexpr int BOFF  = 3 * TERMB;
static constexpr int BUFB  = 6 * TERMB;   // 61440
static constexpr int SMEMB = 2 * BUFB;    // 122880

template<int KTOT, bool GELU>
__global__ __launch_bounds__(256, 1)
void gemm_mma(const __nv_bfloat16* __restrict__ A0, const __nv_bfloat16* __restrict__ A1,
              const __nv_bfloat16* __restrict__ A2,
              const __nv_bfloat16* __restrict__ Bt0, const __nv_bfloat16* __restrict__ Bt1,
              const __nv_bfloat16* __restrict__ Bt2,
              const float* __restrict__ bias, const float* __restrict__ tw, float t_feat,
              float* __restrict__ outF,
              __nv_bfloat16* __restrict__ H0, __nv_bfloat16* __restrict__ H1,
              __nv_bfloat16* __restrict__ H2, int Ntot)
{
    extern __shared__ char smem[];
    const uint32_t sb = smem_u32(smem);
    const int tid = threadIdx.x, lane = tid & 31, wid = tid >> 5;
    const int m0 = blockIdx.y * 128, n0 = blockIdx.x * 128;
    const int wm = (wid >> 2) * 64, wn = (wid & 3) * 32;

    const __nv_bfloat16* At[3] = { A0, A1, A2 };
    const __nv_bfloat16* Bt[3] = { Bt0, Bt1, Bt2 };

    float acc[4][4][4];
#pragma unroll
    for (int a = 0; a < 4; a++)
#pragma unroll
        for (int b = 0; b < 4; b++)
#pragma unroll
            for (int c = 0; c < 4; c++) acc[a][b][c] = 0.0f;

    auto load_tile = [&](int kt, int buf) {
        uint32_t base = sb + buf * BUFB;
#pragma unroll
        for (int i = 0; i < 6; i++) {
            int t = tid + i * 256;
            int term = t >> 9, rem = t & 511;
            int row = rem >> 2, ch = rem & 3;
            cp_async16(base + term * TERMB + row * 80 + ch * 16,
                       At[term] + (size_t)(m0 + row) * KTOT + kt * 32 + ch * 8);
        }
#pragma unroll
        for (int i = 0; i < 6; i++) {
            int t = tid + i * 256;
            int term = t >> 9, rem = t & 511;
            int row = rem >> 2, ch = rem & 3;
            cp_async16(base + BOFF + term * TERMB + row * 80 + ch * 16,
                       Bt[term] + (size_t)(n0 + row) * KTOT + kt * 32 + ch * 8);
        }
        asm volatile("cp.async.commit_group;" ::: "memory");
    };

    constexpr int NKT = KTOT / 32;
    load_tile(0, 0);
    int buf = 0;

    const int PA[6] = { 0, 0, 1, 1, 0, 2 };
    const int PB[6] = { 0, 1, 0, 1, 2, 0 };

#pragma unroll 1
    for (int kt = 0; kt < NKT; kt++) {
        if (kt + 1 < NKT) {
            load_tile(kt + 1, buf ^ 1);
            asm volatile("cp.async.wait_group 1;" ::: "memory");
        } else {
            asm volatile("cp.async.wait_group 0;" ::: "memory");
        }
        __syncthreads();

        uint32_t base = sb + buf * BUFB;
#pragma unroll
        for (int kk = 0; kk < 2; kk++) {
            uint32_t aF[3][4][4];
            uint32_t bF[3][4][2];
#pragma unroll
            for (int t = 0; t < 3; t++) {
#pragma unroll
                for (int mi = 0; mi < 4; mi++) {
                    uint32_t addr = base + t * TERMB
                        + (wm + mi * 16 + (lane & 15)) * 80
                        + kk * 32 + (lane >> 4) * 16;
                    ldsm_x4(aF[t][mi], addr);
                }
#pragma unroll
                for (int nt = 0; nt < 2; nt++) {
                    int row = wn + nt * 16 + ((lane >> 4) & 1) * 8 + (lane & 7);
                    uint32_t addr = base + BOFF + t * TERMB
                        + row * 80 + kk * 32 + ((lane >> 3) & 1) * 16;
                    uint32_t r[4];
                    ldsm_x4(r, addr);
                    bF[t][nt * 2][0]     = r[0]; bF[t][nt * 2][1]     = r[1];
                    bF[t][nt * 2 + 1][0] = r[2]; bF[t][nt * 2 + 1][1] = r[3];
                }
            }
#pragma unroll
            for (int p = 0; p < 6; p++) {
#pragma unroll
                for (int mi = 0; mi < 4; mi++)
#pragma unroll
                    for (int ni = 0; ni < 4; ni++)
                        mma16816(acc[mi][ni], aF[PA[p]][mi], bF[PB[p]][ni]);
            }
        }
        __syncthreads();
        buf ^= 1;
    }

    // ---- epilogue ----
#pragma unroll
    for (int mi = 0; mi < 4; mi++) {
#pragma unroll
        for (int ni = 0; ni < 4; ni++) {
            int r0 = m0 + wm + mi * 16 + (lane >> 2);
            int r1 = r0 + 8;
            int c  = n0 + wn + ni * 8 + (lane & 3) * 2;
            float bz0 = __ldg(bias + c);
            float bz1 = __ldg(bias + c + 1);
            if (GELU) { bz0 += t_feat * __ldg(tw + c); bz1 += t_feat * __ldg(tw + c + 1); }
            float v00 = acc[mi][ni][0] + bz0;
            float v01 = acc[mi][ni][1] + bz1;
            float v10 = acc[mi][ni][2] + bz0;
            float v11 = acc[mi][ni][3] + bz1;
            if (GELU) {
                v00 = gelu_f(v00); v01 = gelu_f(v01);
                v10 = gelu_f(v10); v11 = gelu_f(v11);
                unsigned short a0, a1, a2, b0, b1, b2;
                size_t o0 = (size_t)r0 * Ntot + c, o1 = (size_t)r1 * Ntot + c;
                split3(v00, a0, a1, a2); split3(v01, b0, b1, b2);
                *(uint32_t*)(H0 + o0) = (uint32_t)a0 | ((uint32_t)b0 << 16);
                *(uint32_t*)(H1 + o0) = (uint32_t)a1 | ((uint32_t)b1 << 16);
                *(uint32_t*)(H2 + o0) = (uint32_t)a2 | ((uint32_t)b2 << 16);
                split3(v10, a0, a1, a2); split3(v11, b0, b1, b2);
                *(uint32_t*)(H0 + o1) = (uint32_t)a0 | ((uint32_t)b0 << 16);
                *(uint32_t*)(H1 + o1) = (uint32_t)a1 | ((uint32_t)b1 << 16);
                *(uint32_t*)(H2 + o1) = (uint32_t)a2 | ((uint32_t)b2 << 16);
            } else {
                *(float2*)(outF + (size_t)r0 * Ntot + c) = make_float2(v00, v01);
                *(float2*)(outF + (size_t)r1 * Ntot + c) = make_float2(v10, v11);
            }
        }
    }
}

// ---------------- entropy map + obs_err partial stats ----------------
__global__ __launch_bounds__(256)
void stats_k(const float* __restrict__ z, const float* __restrict__ y,
             const float* __restrict__ msk)
{
    int tid = threadIdx.x;
    int i = blockIdx.x * 256 + tid;

    float sa = 0.0f;
#pragma unroll
    for (int b = 0; b < B_; b++) sa += fabsf(g_eps[(size_t)b * LC_ + i]);
    g_ent[i] = sa * (1.0f / B_);

    float s = 0.0f, sq = 0.0f;
#pragma unroll
    for (int b = 0; b < B_; b++) {
        size_t o = (size_t)b * LC_ + i;
        float e = (z[o] - y[o]) * msk[o];
        s += e; sq += e * e;
    }
    __shared__ float rs[256], rq[256];
    rs[tid] = s; rq[tid] = sq;
    __syncthreads();
    for (int st = 128; st > 0; st >>= 1) {
        if (tid < st) { rs[tid] += rs[tid + st]; rq[tid] += rq[tid + st]; }
        __syncthreads();
    }
    if (tid == 0) { g_part[blockIdx.x] = rs[0]; g_part[512 + blockIdx.x] = rq[0]; }
}

// ---------------- hierarchical pooling ----------------
__global__ __launch_bounds__(256)
void pool_k()
{
    int t = blockIdx.x * 256 + threadIdx.x;
    int w, idx; float* dst;
    if      (t < 32768) { w = 2; dst = g_p1; idx = t; }
    else if (t < 40960) { w = 4; dst = g_p2; idx = t - 32768; }
    else if (t < 43008) { w = 8; dst = g_p3; idx = t - 40960; }
    else return;
    int Cs = C_ / w;
    int pr = idx / Cs, pc = idx % Cs;
    float s = 0.0f;
    for (int a = 0; a < w; a++)
        for (int b = 0; b < w; b++)
            s += g_ent[(pr * w + a) * C_ + pc * w + b];
    dst[idx] = s / (float)(w * w);
}

// ---------------- radix select (warp-aggregated) + var finalize ----------
__global__ __launch_bounds__(1024)
void select_k()
{
    int bs = blockIdx.x;
    int tid = threadIdx.x;
    int lane = tid & 31;

    if (bs == 4) {
        __shared__ float rs[1024], rq[1024];
        rs[tid] = (tid < 512) ? g_part[tid] : 0.0f;
        rq[tid] = (tid < 512) ? g_part[512 + tid] : 0.0f;
        __syncthreads();
        for (int st = 512; st > 0; st >>= 1) {
            if (tid < st) { rs[tid] += rs[tid + st]; rq[tid] += rq[tid + st]; }
            __syncthreads();
        }
        if (tid == 0) { g_stats[0] = rs[0]; g_stats[1] = rq[0]; }
        return;
    }

    const float* data; int n, K;
    switch (bs) {
        case 0: data = g_ent; n = 131072; K = 26214; break;
        case 1: data = g_p1;  n = 32768;  K = 6553;  break;
        case 2: data = g_p2;  n = 8192;   K = 1638;  break;
        default:data = g_p3;  n = 2048;   K = 409;   break;
    }

    __shared__ unsigned hist[256];
    __shared__ unsigned s_pref, s_k;
    unsigned pref = 0, kk = (unsigned)K;

    for (int p = 0; p < 4; p++) {
        int shift = 24 - 8 * p;
        unsigned mask_hi = (p == 0) ? 0u : (0xFFFFFFFFu << (32 - 8 * p));
        if (tid < 256) hist[tid] = 0;
        __syncthreads();
        for (int i = tid; i < n; i += 1024) {
            unsigned u = __float_as_uint(data[i]);
            bool ok = ((u & mask_hi) == pref);
            unsigned bin = (u >> shift) & 255;
            unsigned valid = __ballot_sync(0xFFFFFFFFu, ok);
            unsigned same  = __match_any_sync(0xFFFFFFFFu, bin);
            if (ok) {
                unsigned mm = same & valid;
                if ((int)(__ffs(mm) - 1) == lane)
                    atomicAdd(&hist[bin], __popc(mm));
            }
        }
        __syncthreads();
        if (tid == 0) {
            unsigned cum = 0; int sel = 0;
            for (int b = 255; b >= 0; b--) {
                unsigned c = hist[b];
                if (cum + c >= kk) { sel = b; break; }
                cum += c;
            }
            s_pref = pref | ((unsigned)sel << shift);
            s_k = kk - cum;
        }
        __syncthreads();
        pref = s_pref; kk = s_k;
        __syncthreads();
    }
    if (tid == 0) g_T[bs] = __uint_as_float(pref);
}

// ---------------- final update ----------------
__global__ __launch_bounds__(256)
void update_k(const float* __restrict__ z, const float* __restrict__ y,
              const float* __restrict__ msk, float* __restrict__ out,
              float base_a, float base_b, float h_lam)
{
    int i = blockIdx.x * 256 + threadIdx.x;
    int l = i / C_, c = i % C_;

    int sfound = -1; float ent = 0.0f;
    float v0 = g_ent[i];
    if (v0 >= g_T[0]) { sfound = 0; ent = v0; }
    else {
        float v1 = g_p1[(l >> 1) * (C_ / 2) + (c >> 1)];
        if (v1 >= g_T[1]) { sfound = 1; ent = v1; }
        else {
            float v2 = g_p2[(l >> 2) * (C_ / 4) + (c >> 2)];
            if (v2 >= g_T[2]) { sfound = 2; ent = v2; }
            else {
                float v3 = g_p3[(l >> 3) * (C_ / 8) + (c >> 3)];
                if (v3 >= g_T[3]) { sfound = 3; ent = v3; }
            }
        }
    }

    if (sfound < 0) {
#pragma unroll
        for (int b = 0; b < B_; b++) {
            size_t o = (size_t)b * LC_ + i;
            out[o] = z[o];
        }
        return;
    }

    const float invN = 1.0f / (float)(B_ * LC_);
    float mean = g_stats[0] * invN;
    float var  = g_stats[1] * invN - mean * mean;
    float inv_d = 1.0f / (var + 1e-8f);

    float om1 = (ent > 0.1f ? 1.0f : 0.0f) + (ent > 0.5f ? 1.0f : 0.0f);
    float corr = 1.0f + om1 * 0.5f * h_lam
               + om1 * (om1 - 1.0f) * (1.0f / 6.0f) * h_lam * h_lam;
    float gs = 2.0f * ent / (ent + 1.0f);
    float bb = base_b * corr;

#pragma unroll
    for (int b = 0; b < B_; b++) {
        size_t o = (size_t)b * LC_ + i;
        float zv = z[o];
        float gd = -(zv - y[o]) * msk[o] * inv_d;
        out[o] = base_a * zv - bb * g_eps[o] + gs * gd;
    }
}

// ---------------- host driver ----------------
extern "C" void kernel_launch(void* const* d_in, const int* in_sizes, int n_in,
                              void* d_out, int out_size)
{
    const float* y   = (const float*)d_in[0];
    const float* msk = (const float*)d_in[1];
    const float* z0  = (const float*)d_in[2];
    const float* W1  = (const float*)d_in[3];
    const float* b1  = (const float*)d_in[4];
    const float* W2  = (const float*)d_in[5];
    const float* b2  = (const float*)d_in[6];
    const float* tw  = (const float*)d_in[7];

    static float ac[1000];
    {
        float run = 1.0f;
        for (int i = 0; i < 1000; i++) {
            float beta = 1e-4f + (0.02f - 1e-4f) * ((float)i / 999.0f);
            run *= (1.0f - beta);
            ac[i] = run;
        }
    }
    auto alpha_at = [&](int i) { return sqrtf(ac[i]); };
    auto sigma_at = [&](int i) { return sqrtf(1.0f - ac[i]); };
    auto lam_at   = [&](int i) { return logf(alpha_at(i)) - logf(sigma_at(i)); };

    float *p_eps, *p_za, *p_zb;
    cudaGetSymbolAddress((void**)&p_eps, g_eps);
    cudaGetSymbolAddress((void**)&p_za,  g_za);
    cudaGetSymbolAddress((void**)&p_zb,  g_zb);
    __nv_bfloat16 *za0, *za1, *za2, *h0, *h1, *h2;
    __nv_bfloat16 *b1t0, *b1t1, *b1t2, *b2t0, *b2t1, *b2t2;
    cudaGetSymbolAddress((void**)&za0, g_za0);
    cudaGetSymbolAddress((void**)&za1, g_za1);
    cudaGetSymbolAddress((void**)&za2, g_za2);
    cudaGetSymbolAddress((void**)&h0,  g_h0);
    cudaGetSymbolAddress((void**)&h1,  g_h1);
    cudaGetSymbolAddress((void**)&h2,  g_h2);
    cudaGetSymbolAddress((void**)&b1t0, g_b1t0);
    cudaGetSymbolAddress((void**)&b1t1, g_b1t1);
    cudaGetSymbolAddress((void**)&b1t2, g_b1t2);
    cudaGetSymbolAddress((void**)&b2t0, g_b2t0);
    cudaGetSymbolAddress((void**)&b2t1, g_b2t1);
    cudaGetSymbolAddress((void**)&b2t2, g_b2t2);

    cudaFuncSetAttribute(gemm_mma<128, true >, cudaFuncAttributeMaxDynamicSharedMemorySize, SMEMB);
    cudaFuncSetAttribute(gemm_mma<512, false>, cudaFuncAttributeMaxDynamicSharedMemorySize, SMEMB);

    const float* zin[4]  = { z0,  p_za, p_zb, p_za };
    float*       zout[4] = { p_za, p_zb, p_za, (float*)d_out };

    prep_k<<<512, 256>>>(W1, W2);

    const int step = 1000 / 4;
    dim3 grid1(H_ / 128, M_ / 128);   // (4, 128)
    dim3 grid2(C_ / 128, M_ / 128);   // (1, 128)

    for (int si = 0; si < 4; si++) {
        int k  = 999 - si * step;
        int kp = k - step; if (kp < 0) kp = 0;
        float t_feat = (float)k / 1000.0f;
        float h_lam  = lam_at(kp) - lam_at(k);
        float base_a = alpha_at(kp) / alpha_at(k);
        float base_b = sigma_at(kp) * (expf(h_lam) - 1.0f);

        splitz_k<<<M_ * C_ / 1024, 256>>>(zin[si]);
        gemm_mma<128, true ><<<grid1, 256, SMEMB>>>(za0, za1, za2, b1t0, b1t1, b1t2,
                                                    b1, tw, t_feat, nullptr, h0, h1, h2, H_);
        gemm_mma<512, false><<<grid2, 256, SMEMB>>>(h0, h1, h2, b2t0, b2t1, b2t2,
                                                    b2, b2, 0.0f, p_eps, nullptr, nullptr, nullptr, C_);
        stats_k <<<LC_ / 256, 256>>>(zin[si], y, msk);
        pool_k  <<<168, 256>>>();
        select_k<<<5, 1024>>>();
        update_k<<<LC_ / 256, 256>>>(zin[si], y, msk, zout[si], base_a, base_b, h_lam);
    }
}

// round 5
// speedup vs baseline: 1.0228x; 1.0228x over previous
#include <cuda_runtime.h>
#include <cuda_bf16.h>
#include <math.h>
#include <stdint.h>

#define B_  16
#define L_  1024
#define C_  128
#define H_  512
#define LC_ (L_*C_)      // 131072
#define M_  (B_*L_)      // 16384

// ---------------- device scratch ----------------
__device__ float g_h  [M_*H_];        // 32 MB hidden activations (fp32)
__device__ float g_eps[M_*C_];
__device__ float g_za [M_*C_];
__device__ float g_zb [M_*C_];
__device__ float g_ent[LC_];
__device__ float g_p1[(L_/2)*(C_/2)];
__device__ float g_p2[(L_/4)*(C_/4)];
__device__ float g_p3[(L_/8)*(C_/8)];
__device__ float g_part[1024];
__device__ float g_T[4];
__device__ float g_stats[2];
// weight splits, transposed [N,K] row-major (K contiguous)
__device__ __nv_bfloat16 g_b1t0[H_*C_], g_b1t1[H_*C_], g_b1t2[H_*C_]; // [512,128]
__device__ __nv_bfloat16 g_b2t0[C_*H_], g_b2t1[C_*H_], g_b2t2[C_*H_]; // [128,512]

// ---------------- helpers ----------------
__device__ __forceinline__ uint32_t smem_u32(const void* p) {
    uint32_t a;
    asm("{ .reg .u64 t; cvta.to.shared.u64 t, %1; cvt.u32.u64 %0, t; }" : "=r"(a) : "l"(p));
    return a;
}
__device__ __forceinline__ void cp_async16(uint32_t s, const void* g) {
    asm volatile("cp.async.cg.shared.global [%0], [%1], 16;" :: "r"(s), "l"(g) : "memory");
}
#define STS64v(addr, r0, r1) \
    asm volatile("st.shared.v2.b32 [%0], {%1,%2};" :: "r"(addr), "r"(r0), "r"(r1) : "memory")
__device__ __forceinline__ void ldsm_x4(uint32_t* r, uint32_t addr) {
    asm volatile("ldmatrix.sync.aligned.m8n8.x4.shared.b16 {%0,%1,%2,%3}, [%4];"
                 : "=r"(r[0]), "=r"(r[1]), "=r"(r[2]), "=r"(r[3]) : "r"(addr));
}
__device__ __forceinline__ void mma16816(float* d, const uint32_t* a, const uint32_t* b) {
    asm volatile(
        "mma.sync.aligned.m16n8k16.row.col.f32.bf16.bf16.f32 "
        "{%0,%1,%2,%3}, {%4,%5,%6,%7}, {%8,%9}, {%0,%1,%2,%3};"
        : "+f"(d[0]), "+f"(d[1]), "+f"(d[2]), "+f"(d[3])
        : "r"(a[0]), "r"(a[1]), "r"(a[2]), "r"(a[3]), "r"(b[0]), "r"(b[1]));
}
__device__ __forceinline__ float gelu_f(float x) {
    float x3 = x * x * x;
    float u  = 0.7978845608028654f * (x + 0.044715f * x3);
    return 0.5f * x * (1.0f + tanhf(u));
}
__device__ __forceinline__ void split3(float x, unsigned short& h0, unsigned short& h1, unsigned short& h2) {
    __nv_bfloat16 b0 = __float2bfloat16_rn(x);
    float r1 = x - __bfloat162float(b0);
    __nv_bfloat16 b1 = __float2bfloat16_rn(r1);
    float r2 = r1 - __bfloat162float(b1);
    __nv_bfloat16 b2 = __float2bfloat16_rn(r2);
    h0 = __bfloat16_as_ushort(b0);
    h1 = __bfloat16_as_ushort(b1);
    h2 = __bfloat16_as_ushort(b2);
}

// ---------------- weight prep: transpose + 3-way split (per replay) ------
__global__ __launch_bounds__(256) void prep_k(const float* __restrict__ W1, const float* __restrict__ W2)
{
    int t = blockIdx.x * 256 + threadIdx.x;   // 131072 total
    float x; int idx;
    __nv_bfloat16 *d0, *d1, *d2;
    if (t < H_ * C_) {                        // B1t [512,128] from W1[128,512]
        idx = t; int n = idx >> 7, k = idx & 127;
        x = W1[k * H_ + n];
        d0 = g_b1t0; d1 = g_b1t1; d2 = g_b1t2;
    } else {                                  // B2t [128,512] from W2[512,128]
        idx = t - H_ * C_; int n = idx >> 9, k = idx & 511;
        x = W2[k * C_ + n];
        d0 = g_b2t0; d1 = g_b2t1; d2 = g_b2t2;
    }
    unsigned short h0, h1, h2;
    split3(x, h0, h1, h2);
    d0[idx] = __ushort_as_bfloat16(h0);
    d1[idx] = __ushort_as_bfloat16(h1);
    d2[idx] = __ushort_as_bfloat16(h2);
}

// ---------------- split-fp32 GEMM via bf16 mma.sync ---------------------
// C[M,Ntot] = A[M,KTOT](fp32, split in-kernel) @ B[Ntot,KTOT]^T(pre-split bf16x3)
// CTA 128x128, BK=32, 512 threads (16 warps, 32x32 warp tiles), double buffered.
static constexpr int TERMB = 10240;   // 128 rows x 80B (64B data + 16B pad)
static constexpr int BOFF  = 3 * TERMB;
static constexpr int BUFB  = 6 * TERMB;   // 61440
static constexpr int SMEMB = 2 * BUFB;    // 122880

template<int KTOT, bool GELU>
__global__ __launch_bounds__(512, 1)
void gemm_mma(const float* __restrict__ A,
              const __nv_bfloat16* __restrict__ Bt0, const __nv_bfloat16* __restrict__ Bt1,
              const __nv_bfloat16* __restrict__ Bt2,
              const float* __restrict__ bias, const float* __restrict__ tw, float t_feat,
              float* __restrict__ out, int Ntot)
{
    extern __shared__ char smem[];
    const uint32_t sb = smem_u32(smem);
    const int tid = threadIdx.x, lane = tid & 31, wid = tid >> 5;
    const int m0 = blockIdx.y * 128, n0 = blockIdx.x * 128;
    const int wm = (wid >> 2) * 32, wn = (wid & 3) * 32;

    const __nv_bfloat16* Bt[3] = { Bt0, Bt1, Bt2 };

    float acc[2][4][4];
#pragma unroll
    for (int a = 0; a < 2; a++)
#pragma unroll
        for (int b = 0; b < 4; b++)
#pragma unroll
            for (int c = 0; c < 4; c++) acc[a][b][c] = 0.0f;

    // A fp32 staging in regs: 2 float4 per thread per k-tile
    int arow[2], ac4[2];
#pragma unroll
    for (int i = 0; i < 2; i++) { int f = tid + i * 512; arow[i] = f >> 3; ac4[i] = f & 7; }
    float4 aReg[2];

    auto ldgA = [&](int kt) {
#pragma unroll
        for (int i = 0; i < 2; i++)
            aReg[i] = *(const float4*)(A + (size_t)(m0 + arow[i]) * KTOT + kt * 32 + ac4[i] * 4);
    };
    auto stsA = [&](int buf) {
        uint32_t base = sb + buf * BUFB;
#pragma unroll
        for (int i = 0; i < 2; i++) {
            float x[4] = { aReg[i].x, aReg[i].y, aReg[i].z, aReg[i].w };
            unsigned short s0[4], s1[4], s2[4];
#pragma unroll
            for (int j = 0; j < 4; j++) split3(x[j], s0[j], s1[j], s2[j]);
            uint32_t addr = base + arow[i] * 80 + ac4[i] * 8;
            STS64v(addr,             (uint32_t)s0[0] | ((uint32_t)s0[1] << 16),
                                     (uint32_t)s0[2] | ((uint32_t)s0[3] << 16));
            STS64v(addr + TERMB,     (uint32_t)s1[0] | ((uint32_t)s1[1] << 16),
                                     (uint32_t)s1[2] | ((uint32_t)s1[3] << 16));
            STS64v(addr + 2 * TERMB, (uint32_t)s2[0] | ((uint32_t)s2[1] << 16),
                                     (uint32_t)s2[2] | ((uint32_t)s2[3] << 16));
        }
    };
    auto cpB = [&](int kt, int buf) {
        uint32_t base = sb + buf * BUFB + BOFF;
#pragma unroll
        for (int i = 0; i < 3; i++) {
            int t = tid + i * 512;
            int term = t >> 9, rem = t & 511;
            int row = rem >> 2, ch = rem & 3;
            cp_async16(base + term * TERMB + row * 80 + ch * 16,
                       Bt[term] + (size_t)(n0 + row) * KTOT + kt * 32 + ch * 8);
        }
        asm volatile("cp.async.commit_group;" ::: "memory");
    };

    constexpr int NKT = KTOT / 32;
    ldgA(0);
    cpB(0, 0);
    int buf = 0;

    const int PA[6] = { 0, 0, 1, 1, 0, 2 };
    const int PB[6] = { 0, 1, 0, 1, 2, 0 };

#pragma unroll 1
    for (int kt = 0; kt < NKT; kt++) {
        stsA(buf);
        if (kt + 1 < NKT) {
            cpB(kt + 1, buf ^ 1);
            ldgA(kt + 1);
            asm volatile("cp.async.wait_group 1;" ::: "memory");
        } else {
            asm volatile("cp.async.wait_group 0;" ::: "memory");
        }
        __syncthreads();

        uint32_t base = sb + buf * BUFB;
#pragma unroll
        for (int kk = 0; kk < 2; kk++) {
            uint32_t aF[3][2][4];
            uint32_t bF[3][4][2];
#pragma unroll
            for (int t = 0; t < 3; t++) {
#pragma unroll
                for (int mi = 0; mi < 2; mi++) {
                    uint32_t addr = base + t * TERMB
                        + (wm + mi * 16 + (lane & 15)) * 80
                        + kk * 32 + (lane >> 4) * 16;
                    ldsm_x4(aF[t][mi], addr);
                }
#pragma unroll
                for (int nt = 0; nt < 2; nt++) {
                    int row = wn + nt * 16 + ((lane >> 4) & 1) * 8 + (lane & 7);
                    uint32_t addr = base + BOFF + t * TERMB
                        + row * 80 + kk * 32 + ((lane >> 3) & 1) * 16;
                    uint32_t r[4];
                    ldsm_x4(r, addr);
                    bF[t][nt * 2][0]     = r[0]; bF[t][nt * 2][1]     = r[1];
                    bF[t][nt * 2 + 1][0] = r[2]; bF[t][nt * 2 + 1][1] = r[3];
                }
            }
#pragma unroll
            for (int p = 0; p < 6; p++) {
#pragma unroll
                for (int mi = 0; mi < 2; mi++)
#pragma unroll
                    for (int ni = 0; ni < 4; ni++)
                        mma16816(acc[mi][ni], aF[PA[p]][mi], bF[PB[p]][ni]);
            }
        }
        __syncthreads();
        buf ^= 1;
    }

    // ---- epilogue: bias (+time) (+gelu), fp32 float2 stores ----
#pragma unroll
    for (int mi = 0; mi < 2; mi++) {
#pragma unroll
        for (int ni = 0; ni < 4; ni++) {
            int r0 = m0 + wm + mi * 16 + (lane >> 2);
            int r1 = r0 + 8;
            int c  = n0 + wn + ni * 8 + (lane & 3) * 2;
            float bz0 = __ldg(bias + c);
            float bz1 = __ldg(bias + c + 1);
            if (GELU) { bz0 += t_feat * __ldg(tw + c); bz1 += t_feat * __ldg(tw + c + 1); }
            float v00 = acc[mi][ni][0] + bz0;
            float v01 = acc[mi][ni][1] + bz1;
            float v10 = acc[mi][ni][2] + bz0;
            float v11 = acc[mi][ni][3] + bz1;
            if (GELU) {
                v00 = gelu_f(v00); v01 = gelu_f(v01);
                v10 = gelu_f(v10); v11 = gelu_f(v11);
            }
            *(float2*)(out + (size_t)r0 * Ntot + c) = make_float2(v00, v01);
            *(float2*)(out + (size_t)r1 * Ntot + c) = make_float2(v10, v11);
        }
    }
}

// ---------------- entropy map + obs_err partial stats ----------------
__global__ __launch_bounds__(256)
void stats_k(const float* __restrict__ z, const float* __restrict__ y,
             const float* __restrict__ msk)
{
    int tid = threadIdx.x;
    int i = blockIdx.x * 256 + tid;

    float sa = 0.0f;
#pragma unroll
    for (int b = 0; b < B_; b++) sa += fabsf(g_eps[(size_t)b * LC_ + i]);
    g_ent[i] = sa * (1.0f / B_);

    float s = 0.0f, sq = 0.0f;
#pragma unroll
    for (int b = 0; b < B_; b++) {
        size_t o = (size_t)b * LC_ + i;
        float e = (z[o] - y[o]) * msk[o];
        s += e; sq += e * e;
    }
    __shared__ float rs[256], rq[256];
    rs[tid] = s; rq[tid] = sq;
    __syncthreads();
    for (int st = 128; st > 0; st >>= 1) {
        if (tid < st) { rs[tid] += rs[tid + st]; rq[tid] += rq[tid + st]; }
        __syncthreads();
    }
    if (tid == 0) { g_part[blockIdx.x] = rs[0]; g_part[512 + blockIdx.x] = rq[0]; }
}

// ---------------- hierarchical pooling ----------------
__global__ __launch_bounds__(256)
void pool_k()
{
    int t = blockIdx.x * 256 + threadIdx.x;
    int w, idx; float* dst;
    if      (t < 32768) { w = 2; dst = g_p1; idx = t; }
    else if (t < 40960) { w = 4; dst = g_p2; idx = t - 32768; }
    else if (t < 43008) { w = 8; dst = g_p3; idx = t - 40960; }
    else return;
    int Cs = C_ / w;
    int pr = idx / Cs, pc = idx % Cs;
    float s = 0.0f;
    for (int a = 0; a < w; a++)
        for (int b = 0; b < w; b++)
            s += g_ent[(pr * w + a) * C_ + pc * w + b];
    dst[idx] = s / (float)(w * w);
}

// ---------------- radix select (warp-aggregated) + var finalize ----------
__global__ __launch_bounds__(1024)
void select_k()
{
    int bs = blockIdx.x;
    int tid = threadIdx.x;
    int lane = tid & 31;

    if (bs == 4) {
        __shared__ float rs[1024], rq[1024];
        rs[tid] = (tid < 512) ? g_part[tid] : 0.0f;
        rq[tid] = (tid < 512) ? g_part[512 + tid] : 0.0f;
        __syncthreads();
        for (int st = 512; st > 0; st >>= 1) {
            if (tid < st) { rs[tid] += rs[tid + st]; rq[tid] += rq[tid + st]; }
            __syncthreads();
        }
        if (tid == 0) { g_stats[0] = rs[0]; g_stats[1] = rq[0]; }
        return;
    }

    const float* data; int n, K;
    switch (bs) {
        case 0: data = g_ent; n = 131072; K = 26214; break;
        case 1: data = g_p1;  n = 32768;  K = 6553;  break;
        case 2: data = g_p2;  n = 8192;   K = 1638;  break;
        default:data = g_p3;  n = 2048;   K = 409;   break;
    }

    __shared__ unsigned hist[256];
    __shared__ unsigned s_pref, s_k;
    unsigned pref = 0, kk = (unsigned)K;

    for (int p = 0; p < 4; p++) {
        int shift = 24 - 8 * p;
        unsigned mask_hi = (p == 0) ? 0u : (0xFFFFFFFFu << (32 - 8 * p));
        if (tid < 256) hist[tid] = 0;
        __syncthreads();
        for (int i = tid; i < n; i += 1024) {
            unsigned u = __float_as_uint(data[i]);
            bool ok = ((u & mask_hi) == pref);
            unsigned bin = (u >> shift) & 255;
            unsigned valid = __ballot_sync(0xFFFFFFFFu, ok);
            unsigned same  = __match_any_sync(0xFFFFFFFFu, bin);
            if (ok) {
                unsigned mm = same & valid;
                if ((int)(__ffs(mm) - 1) == lane)
                    atomicAdd(&hist[bin], __popc(mm));
            }
        }
        __syncthreads();
        if (tid == 0) {
            unsigned cum = 0; int sel = 0;
            for (int b = 255; b >= 0; b--) {
                unsigned c = hist[b];
                if (cum + c >= kk) { sel = b; break; }
                cum += c;
            }
            s_pref = pref | ((unsigned)sel << shift);
            s_k = kk - cum;
        }
        __syncthreads();
        pref = s_pref; kk = s_k;
        __syncthreads();
    }
    if (tid == 0) g_T[bs] = __uint_as_float(pref);
}

// ---------------- final update ----------------
__global__ __launch_bounds__(256)
void update_k(const float* __restrict__ z, const float* __restrict__ y,
              const float* __restrict__ msk, float* __restrict__ out,
              float base_a, float base_b, float h_lam)
{
    int i = blockIdx.x * 256 + threadIdx.x;
    int l = i / C_, c = i % C_;

    int sfound = -1; float ent = 0.0f;
    float v0 = g_ent[i];
    if (v0 >= g_T[0]) { sfound = 0; ent = v0; }
    else {
        float v1 = g_p1[(l >> 1) * (C_ / 2) + (c >> 1)];
        if (v1 >= g_T[1]) { sfound = 1; ent = v1; }
        else {
            float v2 = g_p2[(l >> 2) * (C_ / 4) + (c >> 2)];
            if (v2 >= g_T[2]) { sfound = 2; ent = v2; }
            else {
                float v3 = g_p3[(l >> 3) * (C_ / 8) + (c >> 3)];
                if (v3 >= g_T[3]) { sfound = 3; ent = v3; }
            }
        }
    }

    if (sfound < 0) {
#pragma unroll
        for (int b = 0; b < B_; b++) {
            size_t o = (size_t)b * LC_ + i;
            out[o] = z[o];
        }
        return;
    }

    const float invN = 1.0f / (float)(B_ * LC_);
    float mean = g_stats[0] * invN;
    float var  = g_stats[1] * invN - mean * mean;
    float inv_d = 1.0f / (var + 1e-8f);

    float om1 = (ent > 0.1f ? 1.0f : 0.0f) + (ent > 0.5f ? 1.0f : 0.0f);
    float corr = 1.0f + om1 * 0.5f * h_lam
               + om1 * (om1 - 1.0f) * (1.0f / 6.0f) * h_lam * h_lam;
    float gs = 2.0f * ent / (ent + 1.0f);
    float bb = base_b * corr;

#pragma unroll
    for (int b = 0; b < B_; b++) {
        size_t o = (size_t)b * LC_ + i;
        float zv = z[o];
        float gd = -(zv - y[o]) * msk[o] * inv_d;
        out[o] = base_a * zv - bb * g_eps[o] + gs * gd;
    }
}

// ---------------- host driver ----------------
extern "C" void kernel_launch(void* const* d_in, const int* in_sizes, int n_in,
                              void* d_out, int out_size)
{
    const float* y   = (const float*)d_in[0];
    const float* msk = (const float*)d_in[1];
    const float* z0  = (const float*)d_in[2];
    const float* W1  = (const float*)d_in[3];
    const float* b1  = (const float*)d_in[4];
    const float* W2  = (const float*)d_in[5];
    const float* b2  = (const float*)d_in[6];
    const float* tw  = (const float*)d_in[7];

    static float ac[1000];
    {
        float run = 1.0f;
        for (int i = 0; i < 1000; i++) {
            float beta = 1e-4f + (0.02f - 1e-4f) * ((float)i / 999.0f);
            run *= (1.0f - beta);
            ac[i] = run;
        }
    }
    auto alpha_at = [&](int i) { return sqrtf(ac[i]); };
    auto sigma_at = [&](int i) { return sqrtf(1.0f - ac[i]); };
    auto lam_at   = [&](int i) { return logf(alpha_at(i)) - logf(sigma_at(i)); };

    float *p_h, *p_eps, *p_za, *p_zb;
    cudaGetSymbolAddress((void**)&p_h,   g_h);
    cudaGetSymbolAddress((void**)&p_eps, g_eps);
    cudaGetSymbolAddress((void**)&p_za,  g_za);
    cudaGetSymbolAddress((void**)&p_zb,  g_zb);
    __nv_bfloat16 *b1t0, *b1t1, *b1t2, *b2t0, *b2t1, *b2t2;
    cudaGetSymbolAddress((void**)&b1t0, g_b1t0);
    cudaGetSymbolAddress((void**)&b1t1, g_b1t1);
    cudaGetSymbolAddress((void**)&b1t2, g_b1t2);
    cudaGetSymbolAddress((void**)&b2t0, g_b2t0);
    cudaGetSymbolAddress((void**)&b2t1, g_b2t1);
    cudaGetSymbolAddress((void**)&b2t2, g_b2t2);

    cudaFuncSetAttribute(gemm_mma<128, true >, cudaFuncAttributeMaxDynamicSharedMemorySize, SMEMB);
    cudaFuncSetAttribute(gemm_mma<512, false>, cudaFuncAttributeMaxDynamicSharedMemorySize, SMEMB);

    const float* zin[4]  = { z0,  p_za, p_zb, p_za };
    float*       zout[4] = { p_za, p_zb, p_za, (float*)d_out };

    prep_k<<<512, 256>>>(W1, W2);

    const int step = 1000 / 4;
    dim3 grid1(H_ / 128, M_ / 128);   // (4, 128)
    dim3 grid2(C_ / 128, M_ / 128);   // (1, 128)

    for (int si = 0; si < 4; si++) {
        int k  = 999 - si * step;
        int kp = k - step; if (kp < 0) kp = 0;
        float t_feat = (float)k / 1000.0f;
        float h_lam  = lam_at(kp) - lam_at(k);
        float base_a = alpha_at(kp) / alpha_at(k);
        float base_b = sigma_at(kp) * (expf(h_lam) - 1.0f);

        gemm_mma<128, true ><<<grid1, 512, SMEMB>>>(zin[si], b1t0, b1t1, b1t2,
                                                    b1, tw, t_feat, p_h, H_);
        gemm_mma<512, false><<<grid2, 512, SMEMB>>>(p_h, b2t0, b2t1, b2t2,
                                                    b2, b2, 0.0f, p_eps, C_);
        stats_k <<<LC_ / 256, 256>>>(zin[si], y, msk);
        pool_k  <<<168, 256>>>();
        select_k<<<5, 1024>>>();
        update_k<<<LC_ / 256, 256>>>(zin[si], y, msk, zout[si], base_a, base_b, h_lam);
    }
}